// round 13
// baseline (speedup 1.0000x reference)
#include <cuda_runtime.h>
#include <cuda_fp16.h>
#include <cstdint>

#define NROWS 8192
#define DIM 128
#define KSPLIT 8
#define KSLICE (NROWS / KSPLIT)   // 1024
#define NCHUNK KSPLIT             // rowsum chunks == GEMM k-slices
#define NTICKET 256               // 32 rows per ticket

__device__ float g_dis[NROWS];
__device__ __half g_yh[(size_t)NROWS * DIM];          // Y fp16 k-major (reduce)
__device__ __half g_yt[(size_t)DIM * NROWS];          // Y^T fp16 n-major (GEMM B)
__device__ __half g_parth[KSPLIT][(size_t)NROWS * DIM];  // split-K partials fp16
__device__ int g_ticket;
__device__ int g_chunk_done[NCHUNK];

static __device__ __forceinline__ uint32_t s2u(const void* p) {
    uint32_t a;
    asm("{ .reg .u64 t; cvta.to.shared.u64 t, %1; cvt.u32.u64 %0, t; }" : "=r"(a) : "l"(p));
    return a;
}

// ===================== kernel 1: Y = X W^T (no dis!), fp16 both layouts + sync reset =====================
__global__ void __launch_bounds__(256) z_kernel(const float* __restrict__ X,
                                                const float* __restrict__ W) {
    if (blockIdx.x == 0 && threadIdx.x < NCHUNK + 1) {   // reset work-queue state each launch
        if (threadIdx.x == 0) g_ticket = 0;
        else g_chunk_done[threadIdx.x - 1] = 0;
    }
    __shared__ float4 Xs4[32 * 32];
    __shared__ float T[128][33];
    int tid = threadIdx.x;
    int j0 = blockIdx.x * 32;
    const float4* Xg = reinterpret_cast<const float4*>(X) + (size_t)j0 * 32;
    for (int i = tid; i < 1024; i += 256) Xs4[i] = Xg[i];
    __syncthreads();

    int n = tid & 127, half = tid >> 7;
    float acc[16];
    #pragma unroll
    for (int jj = 0; jj < 16; jj++) acc[jj] = 0.f;

    const float4* Wr = reinterpret_cast<const float4*>(W) + (size_t)n * 32;
    #pragma unroll 4
    for (int c4 = 0; c4 < 32; c4++) {
        float4 w = __ldg(Wr + c4);
        #pragma unroll
        for (int jj = 0; jj < 16; jj++) {
            float4 x = Xs4[(half * 16 + jj) * 32 + c4];
            acc[jj] += x.x * w.x + x.y * w.y + x.z * w.z + x.w * w.w;
        }
    }
    #pragma unroll
    for (int jj = 0; jj < 16; jj++) {
        int j = j0 + half * 16 + jj;
        T[n][half * 16 + jj] = acc[jj];
        g_yh[(size_t)j * DIM + n] = __float2half_rn(acc[jj]);
    }
    __syncthreads();
    #pragma unroll
    for (int it = 0; it < 4; it++) {
        int idx = it * 256 + tid;
        int nn = idx >> 3, j4 = idx & 7;
        __half2 h0 = __floats2half2_rn(T[nn][j4 * 4], T[nn][j4 * 4 + 1]);
        __half2 h1 = __floats2half2_rn(T[nn][j4 * 4 + 2], T[nn][j4 * 4 + 3]);
        uint2 pk;
        pk.x = *reinterpret_cast<uint32_t*>(&h0);
        pk.y = *reinterpret_cast<uint32_t*>(&h1);
        *reinterpret_cast<uint2*>(&g_yt[(size_t)nn * NROWS + j0 + j4 * 4]) = pk;
    }
}

// ===================== kernel 2: FUSED rowsum + split-K fp16 GEMM =====================
#define BM 256
#define BK 32
#define BSTGN 4
#define ASTR 40
#define AHSTG (BM * ASTR)
#define BSTR 40
#define BSTG (DIM * BSTR)
#define SMEM_BYTES ((2 * AHSTG + BSTGN * BSTG) * 2)  // 81920 B

static __device__ __forceinline__ void mma_f16(float* c, const uint32_t* a, const uint32_t* b) {
    asm volatile(
        "mma.sync.aligned.m16n8k16.row.col.f32.f16.f16.f32 "
        "{%0,%1,%2,%3}, {%4,%5,%6,%7}, {%8,%9}, {%0,%1,%2,%3};"
        : "+f"(c[0]), "+f"(c[1]), "+f"(c[2]), "+f"(c[3])
        : "r"(a[0]), "r"(a[1]), "r"(a[2]), "r"(a[3]), "r"(b[0]), "r"(b[1]));
}

static __device__ __forceinline__ void ldsm4(uint32_t* r, uint32_t addr) {
    asm volatile("ldmatrix.sync.aligned.m8n8.x4.shared.b16 {%0,%1,%2,%3}, [%4];"
                 : "=r"(r[0]), "=r"(r[1]), "=r"(r[2]), "=r"(r[3]) : "r"(addr));
}

// grid: (KSPLIT, NROWS/BM) = (8, 32); slice-major so wave-1 covers every slice
__global__ void __launch_bounds__(256, 1) gemm_fused(const float* __restrict__ A) {
    extern __shared__ __half smh[];
    __half* sAh = smh;                 // [2][AHSTG]
    __half* sB = smh + 2 * AHSTG;      // [BSTGN][BSTG]
    __shared__ int st;

    int tid = threadIdx.x, wid = tid >> 5, lane = tid & 31;
    int gid = lane >> 2, tig = lane & 3;
    const int slice = blockIdx.x;
    const int m0 = blockIdx.y * BM;
    const int kbase = slice * KSLICE;

    // ---- B prologue first: cp.async overlaps the rowsum phase (Y ready: z ran before) ----
    const int b_r2 = tid >> 2, b_c2 = tid & 3;
    auto issueB = [&](int stage, int buf) {
        int kk = kbase + stage * BK;
        #pragma unroll
        for (int it = 0; it < 2; it++) {
            int idx = it * 256 + tid;
            int r = idx >> 2, c = idx & 3;
            const __half* gp = g_yt + (size_t)r * NROWS + kk + c * 8;
            uint32_t sb = s2u(sB + buf * BSTG + r * BSTR + c * 8);
            asm volatile("cp.async.cg.shared.global [%0], [%1], 16;" :: "r"(sb), "l"(gp));
        }
        asm volatile("cp.async.commit_group;");
    };
    issueB(0, 0); issueB(1, 1); issueB(2, 2);

    // ---- Phase 1: dynamic rowsum work-queue (ticket = 32 rows) ----
    {
        const float4* A4 = reinterpret_cast<const float4*>(A);
        int rsub = tid >> 3, seg = tid & 7;           // 32 rows/ticket, 8 threads/row
        while (true) {
            if (tid == 0) {
                int done = atomicAdd(&g_chunk_done[slice], 0);
                st = (done >= KSLICE) ? -1 : atomicAdd(&g_ticket, 1);
            }
            __syncthreads();
            int t = st;
            __syncthreads();
            if (t < 0 || t >= NTICKET) break;
            int row = t * 32 + rsub;
            const float4* rp = A4 + (size_t)row * (NROWS / 4);
            float s = 0.f;
            #pragma unroll 8
            for (int it = 0; it < 256; it++) {
                float4 v = __ldcs(rp + seg + it * 8);  // 8 lanes -> 128B contiguous
                s += (v.x + v.y) + (v.z + v.w);
            }
            #pragma unroll
            for (int o = 4; o; o >>= 1) s += __shfl_xor_sync(0xffffffffu, s, o, 8);
            if (seg == 0) g_dis[row] = rsqrtf(s + 1.0f);
            __syncthreads();
            if (tid == 0) {
                __threadfence();
                atomicAdd(&g_chunk_done[t >> 5], 32);  // 32 tickets per 1024-row chunk
            }
        }
        if (tid == 0) {
            while (atomicAdd(&g_chunk_done[slice], 0) < KSLICE) __nanosleep(200);
        }
        __syncthreads();
        __threadfence();
    }

    // ---- Phase 2: GEMM on k-slice [kbase, kbase+1024), dis folded into A conversion ----
    const int wm0 = (wid >> 1) * 64, wn0 = (wid & 1) * 64;

    float acc[4][8][4];
    #pragma unroll
    for (int mf = 0; mf < 4; mf++)
        #pragma unroll
        for (int nf = 0; nf < 8; nf++)
            #pragma unroll
            for (int q = 0; q < 4; q++) acc[mf][nf][q] = 0.f;

    const int a_row = lane & 15;
    const uint32_t a_koff = (uint32_t)(lane >> 4) * 16;
    const int b_row = (lane & 7) | ((lane >> 4) << 3);
    const uint32_t b_koff = (uint32_t)((lane >> 3) & 1) * 16;

    const int ar_r = tid >> 3, ar_c = tid & 7;
    float4 areg[8];
    float4 dis4;

    auto ldgA = [&](int stage) {
        int kk = kbase + stage * BK;
        const float* gp0 = A + (size_t)(m0 + ar_r) * NROWS + kk + ar_c * 4;
        dis4 = *reinterpret_cast<const float4*>(&g_dis[kk + ar_c * 4]);
        #pragma unroll
        for (int it = 0; it < 8; it++)
            areg[it] = __ldcs(reinterpret_cast<const float4*>(gp0 + (size_t)(it * 32) * NROWS));
    };
    auto stsA = [&](int slot) {
        __half* dst0 = sAh + slot * AHSTG + ar_r * ASTR + ar_c * 4;
        #pragma unroll
        for (int it = 0; it < 8; it++) {
            __half2 h0 = __floats2half2_rn(areg[it].x * dis4.x, areg[it].y * dis4.y);
            __half2 h1 = __floats2half2_rn(areg[it].z * dis4.z, areg[it].w * dis4.w);
            uint2 pk;
            pk.x = *reinterpret_cast<uint32_t*>(&h0);
            pk.y = *reinterpret_cast<uint32_t*>(&h1);
            *reinterpret_cast<uint2*>(dst0 + it * 32 * ASTR) = pk;
        }
    };

    ldgA(0);

    const int NS = KSLICE / BK;  // 32
    for (int i = 0; i < NS; i++) {
        stsA(i & 1);
        if (i + 1 < NS) ldgA(i + 1);
        asm volatile("cp.async.wait_group %0;" :: "n"(BSTGN - 2));
        __syncthreads();
        if (i + 3 < NS) issueB(i + 3, (i + 3) & (BSTGN - 1));

        uint32_t a_s = s2u(sAh + (i & 1) * AHSTG);
        uint32_t b_s = s2u(sB + (i & (BSTGN - 1)) * BSTG);

        #pragma unroll
        for (int ks = 0; ks < 2; ks++) {
            uint32_t k0h = ks * 16;
            uint32_t ar[4][4], br[4][4];
            #pragma unroll
            for (int mf = 0; mf < 4; mf++)
                ldsm4(ar[mf], a_s + 2u * ((wm0 + mf * 16 + a_row) * ASTR + k0h) + a_koff);
            #pragma unroll
            for (int t = 0; t < 4; t++)
                ldsm4(br[t], b_s + 2u * ((wn0 + t * 16 + b_row) * BSTR + k0h) + b_koff);
            #pragma unroll
            for (int mf = 0; mf < 4; mf++)
                #pragma unroll
                for (int t = 0; t < 4; t++) {
                    uint32_t bt0[2] = {br[t][0], br[t][1]};
                    uint32_t bt1[2] = {br[t][2], br[t][3]};
                    mma_f16(acc[mf][2 * t], ar[mf], bt0);
                    mma_f16(acc[mf][2 * t + 1], ar[mf], bt1);
                }
        }
    }

    __half* P = g_parth[slice];
    #pragma unroll
    for (int mf = 0; mf < 4; mf++) {
        int r0 = m0 + wm0 + mf * 16 + gid;
        #pragma unroll
        for (int nf = 0; nf < 8; nf++) {
            int c = wn0 + nf * 8 + 2 * tig;
            __half2 p0 = __floats2half2_rn(acc[mf][nf][0], acc[mf][nf][1]);
            __half2 p1 = __floats2half2_rn(acc[mf][nf][2], acc[mf][nf][3]);
            *reinterpret_cast<__half2*>(&P[(size_t)r0 * DIM + c]) = p0;
            *reinterpret_cast<__half2*>(&P[(size_t)(r0 + 8) * DIM + c]) = p1;
        }
    }
}

// ===================== kernel 3: out = dis .* (sum P + dis .* Y) + b =====================
__global__ void __launch_bounds__(256) reduce_kernel(const float* __restrict__ bias,
                                                     float* __restrict__ out) {
    int idx = blockIdx.x * 256 + threadIdx.x;     // float4-out index
    int row = idx >> 5, n4 = idx & 31;
    float d = g_dis[row];
    float4 bb = __ldg(reinterpret_cast<const float4*>(bias) + n4);

    float sx = 0.f, sy = 0.f, sz = 0.f, sw = 0.f;
    #pragma unroll
    for (int k = 0; k < KSPLIT; k++) {
        uint2 p = *reinterpret_cast<const uint2*>(&g_parth[k][(size_t)idx * 4]);
        float2 a0 = __half22float2(*reinterpret_cast<__half2*>(&p.x));
        float2 a1 = __half22float2(*reinterpret_cast<__half2*>(&p.y));
        sx += a0.x; sy += a0.y; sz += a1.x; sw += a1.y;
    }
    uint2 yv = *reinterpret_cast<const uint2*>(&g_yh[(size_t)idx * 4]);
    float2 y0 = __half22float2(*reinterpret_cast<__half2*>(&yv.x));
    float2 y1 = __half22float2(*reinterpret_cast<__half2*>(&yv.y));

    float4 o;
    o.x = d * (sx + d * y0.x) + bb.x;
    o.y = d * (sy + d * y0.y) + bb.y;
    o.z = d * (sz + d * y1.x) + bb.z;
    o.w = d * (sw + d * y1.y) + bb.w;
    reinterpret_cast<float4*>(out)[idx] = o;
}

// ===================== host =====================
extern "C" void kernel_launch(void* const* d_in, const int* in_sizes, int n_in,
                              void* d_out, int out_size) {
    const float* X = (const float*)d_in[0];
    const float* A = (const float*)d_in[1];
    const float* W = (const float*)d_in[2];
    const float* b = (const float*)d_in[3];
    float* out = (float*)d_out;

    z_kernel<<<NROWS / 32, 256>>>(X, W);   // also resets the work-queue state

    cudaFuncSetAttribute(gemm_fused, cudaFuncAttributeMaxDynamicSharedMemorySize, SMEM_BYTES);
    gemm_fused<<<dim3(KSPLIT, NROWS / BM), 256, SMEM_BYTES>>>(A);

    reduce_kernel<<<NROWS * DIM / 4 / 256, 256>>>(b, out);
}

// round 14
// speedup vs baseline: 1.1289x; 1.1289x over previous
#include <cuda_runtime.h>
#include <cuda_fp16.h>
#include <cstdint>

#define NROWS 8192
#define DIM 128
#define KSPLIT 4
#define KSLICE (NROWS / KSPLIT)   // 2048

__device__ float g_dis[NROWS];
__device__ __half g_zh[(size_t)NROWS * DIM];          // G fp16 k-major (reduce G-term)
__device__ __half g_zt[(size_t)DIM * NROWS];          // G^T fp16 n-major (GEMM B)
__device__ __half g_parth[KSPLIT][(size_t)NROWS * DIM];  // split-K partials fp16

static __device__ __forceinline__ uint32_t s2u(const void* p) {
    uint32_t a;
    asm("{ .reg .u64 t; cvta.to.shared.u64 t, %1; cvt.u32.u64 %0, t; }" : "=r"(a) : "l"(p));
    return a;
}

// ===================== kernel 1: row sums -> dis (pure read) =====================
__global__ void __launch_bounds__(256) rowsum_kernel(const float4* __restrict__ A4) {
    int row = blockIdx.x;
    const float4* r = A4 + (size_t)row * (NROWS / 4);
    float s = 0.f;
    #pragma unroll
    for (int p = 0; p < 8; p++) {
        float4 v = __ldcs(r + threadIdx.x + p * 256);
        s += (v.x + v.y) + (v.z + v.w);
    }
    #pragma unroll
    for (int o = 16; o; o >>= 1) s += __shfl_xor_sync(0xffffffffu, s, o);
    __shared__ float ws[8];
    if ((threadIdx.x & 31) == 0) ws[threadIdx.x >> 5] = s;
    __syncthreads();
    if (threadIdx.x < 8) {
        float t = ws[threadIdx.x];
        #pragma unroll
        for (int o = 4; o; o >>= 1) t += __shfl_xor_sync(0xffu, t, o);
        if (threadIdx.x == 0) g_dis[row] = rsqrtf(t + 1.0f);
    }
}

// ===================== kernel 2: G = dis.*(X W^T), FAST: 512 CTAs, 8 acc/thread =====================
__global__ void __launch_bounds__(256) z_kernel(const float* __restrict__ X,
                                                const float* __restrict__ W) {
    __shared__ float4 Xs4[16 * 32];       // 16 rows x 128 floats = 8KB
    __shared__ float T[128][17];          // transpose staging, pad 17 (conflict-free)
    int tid = threadIdx.x;
    int j0 = blockIdx.x * 16;
    const float4* Xg = reinterpret_cast<const float4*>(X) + (size_t)j0 * 32;
    #pragma unroll
    for (int i = 0; i < 2; i++) Xs4[i * 256 + tid] = Xg[i * 256 + tid];
    __syncthreads();

    int n = tid & 127, half = tid >> 7;   // half selects 8-row group
    float acc[8];
    #pragma unroll
    for (int jj = 0; jj < 8; jj++) acc[jj] = 0.f;

    const float4* Wr = reinterpret_cast<const float4*>(W) + (size_t)n * 32;
    #pragma unroll 8
    for (int c4 = 0; c4 < 32; c4++) {
        float4 w = __ldg(Wr + c4);
        #pragma unroll
        for (int jj = 0; jj < 8; jj++) {
            float4 x = Xs4[(half * 8 + jj) * 32 + c4];
            acc[jj] += x.x * w.x + x.y * w.y + x.z * w.z + x.w * w.w;
        }
    }
    #pragma unroll
    for (int jj = 0; jj < 8; jj++) {
        int j = j0 + half * 8 + jj;
        float z = g_dis[j] * acc[jj];
        T[n][half * 8 + jj] = z;
        g_zh[(size_t)j * DIM + n] = __float2half_rn(z);
    }
    __syncthreads();
    // g_zt n-major: 128 n-rows x 16 j = 512 uint2 (4 halves each), 2 per thread
    #pragma unroll
    for (int it = 0; it < 2; it++) {
        int idx = it * 256 + tid;
        int nn = idx >> 2, j4 = idx & 3;
        __half2 h0 = __floats2half2_rn(T[nn][j4 * 4], T[nn][j4 * 4 + 1]);
        __half2 h1 = __floats2half2_rn(T[nn][j4 * 4 + 2], T[nn][j4 * 4 + 3]);
        uint2 pk;
        pk.x = *reinterpret_cast<uint32_t*>(&h0);
        pk.y = *reinterpret_cast<uint32_t*>(&h1);
        *reinterpret_cast<uint2*>(&g_zt[(size_t)nn * NROWS + j0 + j4 * 4]) = pk;
    }
}

// ===================== kernel 3: split-K fp16 GEMM, fp32 A staged through registers =====================
#define BM 256
#define BK 32
#define BSTGN 4
#define ASTR 40
#define AHSTG (BM * ASTR)
#define BSTR 40
#define BSTG (DIM * BSTR)
#define SMEM_BYTES ((2 * AHSTG + BSTGN * BSTG) * 2)  // 81920 B

static __device__ __forceinline__ void mma_f16(float* c, const uint32_t* a, const uint32_t* b) {
    asm volatile(
        "mma.sync.aligned.m16n8k16.row.col.f32.f16.f16.f32 "
        "{%0,%1,%2,%3}, {%4,%5,%6,%7}, {%8,%9}, {%0,%1,%2,%3};"
        : "+f"(c[0]), "+f"(c[1]), "+f"(c[2]), "+f"(c[3])
        : "r"(a[0]), "r"(a[1]), "r"(a[2]), "r"(a[3]), "r"(b[0]), "r"(b[1]));
}

static __device__ __forceinline__ void ldsm4(uint32_t* r, uint32_t addr) {
    asm volatile("ldmatrix.sync.aligned.m8n8.x4.shared.b16 {%0,%1,%2,%3}, [%4];"
                 : "=r"(r[0]), "=r"(r[1]), "=r"(r[2]), "=r"(r[3]) : "r"(addr));
}

__global__ void __launch_bounds__(256, 1) gemm_kernel(const float* __restrict__ A) {
    extern __shared__ __half smh[];
    __half* sAh = smh;                 // [2][AHSTG]
    __half* sB = smh + 2 * AHSTG;      // [BSTGN][BSTG]

    int tid = threadIdx.x, wid = tid >> 5, lane = tid & 31;
    int gid = lane >> 2, tig = lane & 3;
    const int m0 = blockIdx.x * BM;
    const int kbase = blockIdx.y * KSLICE;

    const int wm0 = (wid >> 1) * 64, wn0 = (wid & 1) * 64;

    float acc[4][8][4];
    #pragma unroll
    for (int mf = 0; mf < 4; mf++)
        #pragma unroll
        for (int nf = 0; nf < 8; nf++)
            #pragma unroll
            for (int q = 0; q < 4; q++) acc[mf][nf][q] = 0.f;

    const int a_row = lane & 15;
    const uint32_t a_koff = (uint32_t)(lane >> 4) * 16;
    const int b_row = (lane & 7) | ((lane >> 4) << 3);
    const uint32_t b_koff = (uint32_t)((lane >> 3) & 1) * 16;

    const int ar_r = tid >> 3, ar_c = tid & 7;
    float4 areg[8];

    auto ldgA = [&](int stage) {
        int kk = kbase + stage * BK;
        const float* gp0 = A + (size_t)(m0 + ar_r) * NROWS + kk + ar_c * 4;
        #pragma unroll
        for (int it = 0; it < 8; it++)
            areg[it] = __ldcs(reinterpret_cast<const float4*>(gp0 + (size_t)(it * 32) * NROWS));
    };
    auto stsA = [&](int slot) {
        __half* dst0 = sAh + slot * AHSTG + ar_r * ASTR + ar_c * 4;
        #pragma unroll
        for (int it = 0; it < 8; it++) {
            __half2 h0 = __floats2half2_rn(areg[it].x, areg[it].y);
            __half2 h1 = __floats2half2_rn(areg[it].z, areg[it].w);
            uint2 pk;
            pk.x = *reinterpret_cast<uint32_t*>(&h0);
            pk.y = *reinterpret_cast<uint32_t*>(&h1);
            *reinterpret_cast<uint2*>(dst0 + it * 32 * ASTR) = pk;
        }
    };
    auto issueB = [&](int stage, int buf) {
        int kk = kbase + stage * BK;
        #pragma unroll
        for (int it = 0; it < 2; it++) {
            int idx = it * 256 + tid;
            int r = idx >> 2, c = idx & 3;
            const __half* gp = g_zt + (size_t)r * NROWS + kk + c * 8;
            uint32_t sb = s2u(sB + buf * BSTG + r * BSTR + c * 8);
            asm volatile("cp.async.cg.shared.global [%0], [%1], 16;" :: "r"(sb), "l"(gp));
        }
        asm volatile("cp.async.commit_group;");
    };

    ldgA(0);
    issueB(0, 0); issueB(1, 1); issueB(2, 2);

    const int NS = KSLICE / BK;  // 64
    for (int i = 0; i < NS; i++) {
        stsA(i & 1);
        if (i + 1 < NS) ldgA(i + 1);
        asm volatile("cp.async.wait_group %0;" :: "n"(BSTGN - 2));
        __syncthreads();
        if (i + 3 < NS) issueB(i + 3, (i + 3) & (BSTGN - 1));

        uint32_t a_s = s2u(sAh + (i & 1) * AHSTG);
        uint32_t b_s = s2u(sB + (i & (BSTGN - 1)) * BSTG);

        #pragma unroll
        for (int ks = 0; ks < 2; ks++) {
            uint32_t k0h = ks * 16;
            uint32_t ar[4][4], br[4][4];
            #pragma unroll
            for (int mf = 0; mf < 4; mf++)
                ldsm4(ar[mf], a_s + 2u * ((wm0 + mf * 16 + a_row) * ASTR + k0h) + a_koff);
            #pragma unroll
            for (int t = 0; t < 4; t++)
                ldsm4(br[t], b_s + 2u * ((wn0 + t * 16 + b_row) * BSTR + k0h) + b_koff);
            #pragma unroll
            for (int mf = 0; mf < 4; mf++)
                #pragma unroll
                for (int t = 0; t < 4; t++) {
                    uint32_t bt0[2] = {br[t][0], br[t][1]};
                    uint32_t bt1[2] = {br[t][2], br[t][3]};
                    mma_f16(acc[mf][2 * t], ar[mf], bt0);
                    mma_f16(acc[mf][2 * t + 1], ar[mf], bt1);
                }
        }
    }

    // split-K partials in fp16; acc[mf][nf] covers n = wn0 + nf*8
    __half* P = g_parth[blockIdx.y];
    #pragma unroll
    for (int mf = 0; mf < 4; mf++) {
        int r0 = m0 + wm0 + mf * 16 + gid;
        #pragma unroll
        for (int nf = 0; nf < 8; nf++) {
            int c = wn0 + nf * 8 + 2 * tig;
            __half2 p0 = __floats2half2_rn(acc[mf][nf][0], acc[mf][nf][1]);
            __half2 p1 = __floats2half2_rn(acc[mf][nf][2], acc[mf][nf][3]);
            *reinterpret_cast<__half2*>(&P[(size_t)r0 * DIM + c]) = p0;
            *reinterpret_cast<__half2*>(&P[(size_t)(r0 + 8) * DIM + c]) = p1;
        }
    }
}

// ===================== kernel 4: out = dis .* (sum P + G) + b (fp16 inputs) =====================
__global__ void __launch_bounds__(256) reduce_kernel(const float* __restrict__ bias,
                                                     float* __restrict__ out) {
    int idx = blockIdx.x * 256 + threadIdx.x;     // float4-out index
    int row = idx >> 5, n4 = idx & 31;
    uint2 p0 = *reinterpret_cast<const uint2*>(&g_parth[0][(size_t)idx * 4]);
    uint2 p1 = *reinterpret_cast<const uint2*>(&g_parth[1][(size_t)idx * 4]);
    uint2 p2 = *reinterpret_cast<const uint2*>(&g_parth[2][(size_t)idx * 4]);
    uint2 p3 = *reinterpret_cast<const uint2*>(&g_parth[3][(size_t)idx * 4]);
    uint2 gz = *reinterpret_cast<const uint2*>(&g_zh[(size_t)idx * 4]);
    float d = g_dis[row];
    float4 bb = __ldg(reinterpret_cast<const float4*>(bias) + n4);

    float2 a0 = __half22float2(*reinterpret_cast<__half2*>(&p0.x));
    float2 a1 = __half22float2(*reinterpret_cast<__half2*>(&p0.y));
    float2 b0 = __half22float2(*reinterpret_cast<__half2*>(&p1.x));
    float2 b1 = __half22float2(*reinterpret_cast<__half2*>(&p1.y));
    float2 c0 = __half22float2(*reinterpret_cast<__half2*>(&p2.x));
    float2 c1 = __half22float2(*reinterpret_cast<__half2*>(&p2.y));
    float2 e0 = __half22float2(*reinterpret_cast<__half2*>(&p3.x));
    float2 e1 = __half22float2(*reinterpret_cast<__half2*>(&p3.y));
    float2 g0 = __half22float2(*reinterpret_cast<__half2*>(&gz.x));
    float2 g1 = __half22float2(*reinterpret_cast<__half2*>(&gz.y));

    float4 o;
    o.x = d * (a0.x + b0.x + c0.x + e0.x + g0.x) + bb.x;
    o.y = d * (a0.y + b0.y + c0.y + e0.y + g0.y) + bb.y;
    o.z = d * (a1.x + b1.x + c1.x + e1.x + g1.x) + bb.z;
    o.w = d * (a1.y + b1.y + c1.y + e1.y + g1.y) + bb.w;
    reinterpret_cast<float4*>(out)[idx] = o;
}

// ===================== host =====================
extern "C" void kernel_launch(void* const* d_in, const int* in_sizes, int n_in,
                              void* d_out, int out_size) {
    const float* X = (const float*)d_in[0];
    const float* A = (const float*)d_in[1];
    const float* W = (const float*)d_in[2];
    const float* b = (const float*)d_in[3];
    float* out = (float*)d_out;

    rowsum_kernel<<<NROWS, 256>>>((const float4*)A);
    z_kernel<<<NROWS / 16, 256>>>(X, W);

    cudaFuncSetAttribute(gemm_kernel, cudaFuncAttributeMaxDynamicSharedMemorySize, SMEM_BYTES);
    gemm_kernel<<<dim3(NROWS / BM, KSPLIT), 256, SMEM_BYTES>>>(A);
    reduce_kernel<<<NROWS * DIM / 4 / 256, 256>>>(b, out);
}

// round 15
// speedup vs baseline: 1.1843x; 1.0491x over previous
#include <cuda_runtime.h>
#include <cuda_fp16.h>
#include <cstdint>

#define NROWS 8192
#define DIM 128
#define KSPLIT 4
#define KSLICE (NROWS / KSPLIT)   // 2048
#define ZBLK 512                  // z tiles of 16 rows

__device__ float g_dis[NROWS];
__device__ __half g_yh[(size_t)NROWS * DIM];          // Y fp16 k-major (reduce; NO dis)
__device__ __half g_yt[(size_t)DIM * NROWS];          // Y^T fp16 n-major (GEMM B; NO dis)
__device__ __half g_parth[KSPLIT][(size_t)NROWS * DIM];  // split-K partials fp16

static __device__ __forceinline__ uint32_t s2u(const void* p) {
    uint32_t a;
    asm("{ .reg .u64 t; cvta.to.shared.u64 t, %1; cvt.u32.u64 %0, t; }" : "=r"(a) : "l"(p));
    return a;
}

// ===================== kernel 1: FUSED prep: z-blocks (first) + rowsum blocks =====================
__global__ void __launch_bounds__(256) prep_kernel(const float4* __restrict__ A4,
                                                   const float* __restrict__ X,
                                                   const float* __restrict__ W) {
    __shared__ float4 Xs4[16 * 32];       // 8KB (z path)
    __shared__ float T[128][17];          // 8.7KB (z path)
    __shared__ float ws[8];               // rowsum path
    int tid = threadIdx.x;

    if (blockIdx.x < ZBLK) {
        // ---- z: Y = X W^T (no dis), fp16 both layouts ----
        int j0 = blockIdx.x * 16;
        const float4* Xg = reinterpret_cast<const float4*>(X) + (size_t)j0 * 32;
        #pragma unroll
        for (int i = 0; i < 2; i++) Xs4[i * 256 + tid] = Xg[i * 256 + tid];
        __syncthreads();

        int n = tid & 127, half = tid >> 7;
        float acc[8];
        #pragma unroll
        for (int jj = 0; jj < 8; jj++) acc[jj] = 0.f;

        const float4* Wr = reinterpret_cast<const float4*>(W) + (size_t)n * 32;
        #pragma unroll 8
        for (int c4 = 0; c4 < 32; c4++) {
            float4 w = __ldg(Wr + c4);
            #pragma unroll
            for (int jj = 0; jj < 8; jj++) {
                float4 x = Xs4[(half * 8 + jj) * 32 + c4];
                acc[jj] += x.x * w.x + x.y * w.y + x.z * w.z + x.w * w.w;
            }
        }
        #pragma unroll
        for (int jj = 0; jj < 8; jj++) {
            int j = j0 + half * 8 + jj;
            T[n][half * 8 + jj] = acc[jj];
            g_yh[(size_t)j * DIM + n] = __float2half_rn(acc[jj]);
        }
        __syncthreads();
        #pragma unroll
        for (int it = 0; it < 2; it++) {
            int idx = it * 256 + tid;
            int nn = idx >> 2, j4 = idx & 3;
            __half2 h0 = __floats2half2_rn(T[nn][j4 * 4], T[nn][j4 * 4 + 1]);
            __half2 h1 = __floats2half2_rn(T[nn][j4 * 4 + 2], T[nn][j4 * 4 + 3]);
            uint2 pk;
            pk.x = *reinterpret_cast<uint32_t*>(&h0);
            pk.y = *reinterpret_cast<uint32_t*>(&h1);
            *reinterpret_cast<uint2*>(&g_yt[(size_t)nn * NROWS + j0 + j4 * 4]) = pk;
        }
    } else {
        // ---- rowsum: dis = rsqrt(sum(A_row)+1) ----
        int row = blockIdx.x - ZBLK;
        const float4* r = A4 + (size_t)row * (NROWS / 4);
        float s = 0.f;
        #pragma unroll
        for (int p = 0; p < 8; p++) {
            float4 v = __ldcs(r + tid + p * 256);
            s += (v.x + v.y) + (v.z + v.w);
        }
        #pragma unroll
        for (int o = 16; o; o >>= 1) s += __shfl_xor_sync(0xffffffffu, s, o);
        if ((tid & 31) == 0) ws[tid >> 5] = s;
        __syncthreads();
        if (tid < 8) {
            float t = ws[tid];
            #pragma unroll
            for (int o = 4; o; o >>= 1) t += __shfl_xor_sync(0xffu, t, o);
            if (tid == 0) g_dis[row] = rsqrtf(t + 1.0f);
        }
    }
}

// ===================== kernel 2: split-K fp16 GEMM, dis folded into A conversion =====================
#define BM 256
#define BK 32
#define BSTGN 4
#define ASTR 40
#define AHSTG (BM * ASTR)
#define BSTR 40
#define BSTG (DIM * BSTR)
#define SMEM_BYTES ((2 * AHSTG + BSTGN * BSTG) * 2)  // 81920 B

static __device__ __forceinline__ void mma_f16(float* c, const uint32_t* a, const uint32_t* b) {
    asm volatile(
        "mma.sync.aligned.m16n8k16.row.col.f32.f16.f16.f32 "
        "{%0,%1,%2,%3}, {%4,%5,%6,%7}, {%8,%9}, {%0,%1,%2,%3};"
        : "+f"(c[0]), "+f"(c[1]), "+f"(c[2]), "+f"(c[3])
        : "r"(a[0]), "r"(a[1]), "r"(a[2]), "r"(a[3]), "r"(b[0]), "r"(b[1]));
}

static __device__ __forceinline__ void ldsm4(uint32_t* r, uint32_t addr) {
    asm volatile("ldmatrix.sync.aligned.m8n8.x4.shared.b16 {%0,%1,%2,%3}, [%4];"
                 : "=r"(r[0]), "=r"(r[1]), "=r"(r[2]), "=r"(r[3]) : "r"(addr));
}

__global__ void __launch_bounds__(256, 1) gemm_kernel(const float* __restrict__ A) {
    extern __shared__ __half smh[];
    __half* sAh = smh;                 // [2][AHSTG]
    __half* sB = smh + 2 * AHSTG;      // [BSTGN][BSTG]

    int tid = threadIdx.x, wid = tid >> 5, lane = tid & 31;
    int gid = lane >> 2, tig = lane & 3;
    const int m0 = blockIdx.x * BM;
    const int kbase = blockIdx.y * KSLICE;

    const int wm0 = (wid >> 1) * 64, wn0 = (wid & 1) * 64;

    float acc[4][8][4];
    #pragma unroll
    for (int mf = 0; mf < 4; mf++)
        #pragma unroll
        for (int nf = 0; nf < 8; nf++)
            #pragma unroll
            for (int q = 0; q < 4; q++) acc[mf][nf][q] = 0.f;

    const int a_row = lane & 15;
    const uint32_t a_koff = (uint32_t)(lane >> 4) * 16;
    const int b_row = (lane & 7) | ((lane >> 4) << 3);
    const uint32_t b_koff = (uint32_t)((lane >> 3) & 1) * 16;

    const int ar_r = tid >> 3, ar_c = tid & 7;
    float4 areg[8];
    float4 dis4;

    auto ldgA = [&](int stage) {
        int kk = kbase + stage * BK;
        const float* gp0 = A + (size_t)(m0 + ar_r) * NROWS + kk + ar_c * 4;
        dis4 = *reinterpret_cast<const float4*>(&g_dis[kk + ar_c * 4]);
        #pragma unroll
        for (int it = 0; it < 8; it++)
            areg[it] = __ldcs(reinterpret_cast<const float4*>(gp0 + (size_t)(it * 32) * NROWS));
    };
    auto stsA = [&](int slot) {
        __half* dst0 = sAh + slot * AHSTG + ar_r * ASTR + ar_c * 4;
        #pragma unroll
        for (int it = 0; it < 8; it++) {
            __half2 h0 = __floats2half2_rn(areg[it].x * dis4.x, areg[it].y * dis4.y);
            __half2 h1 = __floats2half2_rn(areg[it].z * dis4.z, areg[it].w * dis4.w);
            uint2 pk;
            pk.x = *reinterpret_cast<uint32_t*>(&h0);
            pk.y = *reinterpret_cast<uint32_t*>(&h1);
            *reinterpret_cast<uint2*>(dst0 + it * 32 * ASTR) = pk;
        }
    };
    auto issueB = [&](int stage, int buf) {
        int kk = kbase + stage * BK;
        #pragma unroll
        for (int it = 0; it < 2; it++) {
            int idx = it * 256 + tid;
            int r = idx >> 2, c = idx & 3;
            const __half* gp = g_yt + (size_t)r * NROWS + kk + c * 8;
            uint32_t sb = s2u(sB + buf * BSTG + r * BSTR + c * 8);
            asm volatile("cp.async.cg.shared.global [%0], [%1], 16;" :: "r"(sb), "l"(gp));
        }
        asm volatile("cp.async.commit_group;");
    };

    ldgA(0);
    issueB(0, 0); issueB(1, 1); issueB(2, 2);

    const int NS = KSLICE / BK;  // 64
    for (int i = 0; i < NS; i++) {
        stsA(i & 1);
        if (i + 1 < NS) ldgA(i + 1);
        asm volatile("cp.async.wait_group %0;" :: "n"(BSTGN - 2));
        __syncthreads();
        if (i + 3 < NS) issueB(i + 3, (i + 3) & (BSTGN - 1));

        uint32_t a_s = s2u(sAh + (i & 1) * AHSTG);
        uint32_t b_s = s2u(sB + (i & (BSTGN - 1)) * BSTG);

        #pragma unroll
        for (int ks = 0; ks < 2; ks++) {
            uint32_t k0h = ks * 16;
            uint32_t ar[4][4], br[4][4];
            #pragma unroll
            for (int mf = 0; mf < 4; mf++)
                ldsm4(ar[mf], a_s + 2u * ((wm0 + mf * 16 + a_row) * ASTR + k0h) + a_koff);
            #pragma unroll
            for (int t = 0; t < 4; t++)
                ldsm4(br[t], b_s + 2u * ((wn0 + t * 16 + b_row) * BSTR + k0h) + b_koff);
            #pragma unroll
            for (int mf = 0; mf < 4; mf++)
                #pragma unroll
                for (int t = 0; t < 4; t++) {
                    uint32_t bt0[2] = {br[t][0], br[t][1]};
                    uint32_t bt1[2] = {br[t][2], br[t][3]};
                    mma_f16(acc[mf][2 * t], ar[mf], bt0);
                    mma_f16(acc[mf][2 * t + 1], ar[mf], bt1);
                }
        }
    }

    __half* P = g_parth[blockIdx.y];
    #pragma unroll
    for (int mf = 0; mf < 4; mf++) {
        int r0 = m0 + wm0 + mf * 16 + gid;
        #pragma unroll
        for (int nf = 0; nf < 8; nf++) {
            int c = wn0 + nf * 8 + 2 * tig;
            __half2 p0 = __floats2half2_rn(acc[mf][nf][0], acc[mf][nf][1]);
            __half2 p1 = __floats2half2_rn(acc[mf][nf][2], acc[mf][nf][3]);
            *reinterpret_cast<__half2*>(&P[(size_t)r0 * DIM + c]) = p0;
            *reinterpret_cast<__half2*>(&P[(size_t)(r0 + 8) * DIM + c]) = p1;
        }
    }
}

// ===================== kernel 3: out = dis .* (sum P + dis .* Y) + b =====================
__global__ void __launch_bounds__(256) reduce_kernel(const float* __restrict__ bias,
                                                     float* __restrict__ out) {
    int idx = blockIdx.x * 256 + threadIdx.x;     // float4-out index
    int row = idx >> 5, n4 = idx & 31;
    uint2 p0 = *reinterpret_cast<const uint2*>(&g_parth[0][(size_t)idx * 4]);
    uint2 p1 = *reinterpret_cast<const uint2*>(&g_parth[1][(size_t)idx * 4]);
    uint2 p2 = *reinterpret_cast<const uint2*>(&g_parth[2][(size_t)idx * 4]);
    uint2 p3 = *reinterpret_cast<const uint2*>(&g_parth[3][(size_t)idx * 4]);
    uint2 yv = *reinterpret_cast<const uint2*>(&g_yh[(size_t)idx * 4]);
    float d = g_dis[row];
    float4 bb = __ldg(reinterpret_cast<const float4*>(bias) + n4);

    float2 a0 = __half22float2(*reinterpret_cast<__half2*>(&p0.x));
    float2 a1 = __half22float2(*reinterpret_cast<__half2*>(&p0.y));
    float2 b0 = __half22float2(*reinterpret_cast<__half2*>(&p1.x));
    float2 b1 = __half22float2(*reinterpret_cast<__half2*>(&p1.y));
    float2 c0 = __half22float2(*reinterpret_cast<__half2*>(&p2.x));
    float2 c1 = __half22float2(*reinterpret_cast<__half2*>(&p2.y));
    float2 e0 = __half22float2(*reinterpret_cast<__half2*>(&p3.x));
    float2 e1 = __half22float2(*reinterpret_cast<__half2*>(&p3.y));
    float2 y0 = __half22float2(*reinterpret_cast<__half2*>(&yv.x));
    float2 y1 = __half22float2(*reinterpret_cast<__half2*>(&yv.y));

    float4 o;
    o.x = d * (a0.x + b0.x + c0.x + e0.x + d * y0.x) + bb.x;
    o.y = d * (a0.y + b0.y + c0.y + e0.y + d * y0.y) + bb.y;
    o.z = d * (a1.x + b1.x + c1.x + e1.x + d * y1.x) + bb.z;
    o.w = d * (a1.y + b1.y + c1.y + e1.y + d * y1.y) + bb.w;
    reinterpret_cast<float4*>(out)[idx] = o;
}

// ===================== host =====================
extern "C" void kernel_launch(void* const* d_in, const int* in_sizes, int n_in,
                              void* d_out, int out_size) {
    const float* X = (const float*)d_in[0];
    const float* A = (const float*)d_in[1];
    const float* W = (const float*)d_in[2];
    const float* b = (const float*)d_in[3];
    float* out = (float*)d_out;

    prep_kernel<<<NROWS + ZBLK, 256>>>((const float4*)A, X, W);

    cudaFuncSetAttribute(gemm_kernel, cudaFuncAttributeMaxDynamicSharedMemorySize, SMEM_BYTES);
    gemm_kernel<<<dim3(NROWS / BM, KSPLIT), 256, SMEM_BYTES>>>(A);
    reduce_kernel<<<NROWS * DIM / 4 / 256, 256>>>(b, out);
}

// round 16
// speedup vs baseline: 1.2457x; 1.0519x over previous
#include <cuda_runtime.h>
#include <cuda_fp16.h>
#include <cstdint>

#define NROWS 8192
#define DIM 128
#define KSPLIT 4
#define KSLICE (NROWS / KSPLIT)   // 2048
#define ZBLK 512                  // z tiles of 16 rows

__device__ float g_dis[NROWS];
__device__ __half g_yh[(size_t)NROWS * DIM];          // Y fp16 k-major (reduce; NO dis)
__device__ __half g_yt[(size_t)DIM * NROWS];          // Y^T fp16 n-major (GEMM B; NO dis)
__device__ __half g_parth[KSPLIT][(size_t)NROWS * DIM];  // split-K partials fp16

static __device__ __forceinline__ uint32_t s2u(const void* p) {
    uint32_t a;
    asm("{ .reg .u64 t; cvta.to.shared.u64 t, %1; cvt.u32.u64 %0, t; }" : "=r"(a) : "l"(p));
    return a;
}

// ===================== kernel 1: FUSED prep: z-blocks (first) + rowsum blocks =====================
// __launch_bounds__(256, 8): cap regs at 32 so the rowsum majority keeps 8 CTAs/SM.
// The z branch (6% of blocks) spills a little to local — acceptable, it's latency work
// hidden under the DRAM stream.
__global__ void __launch_bounds__(256, 8) prep_kernel(const float4* __restrict__ A4,
                                                      const float* __restrict__ X,
                                                      const float* __restrict__ W) {
    __shared__ float4 Xs4[16 * 32];       // 8KB (z path)
    __shared__ float T[128][17];          // 8.7KB (z path)
    __shared__ float ws[8];               // rowsum path
    int tid = threadIdx.x;

    if (blockIdx.x < ZBLK) {
        // ---- z: Y = X W^T (no dis), fp16 both layouts ----
        int j0 = blockIdx.x * 16;
        const float4* Xg = reinterpret_cast<const float4*>(X) + (size_t)j0 * 32;
        #pragma unroll
        for (int i = 0; i < 2; i++) Xs4[i * 256 + tid] = Xg[i * 256 + tid];
        __syncthreads();

        int n = tid & 127, half = tid >> 7;
        float acc[8];
        #pragma unroll
        for (int jj = 0; jj < 8; jj++) acc[jj] = 0.f;

        const float4* Wr = reinterpret_cast<const float4*>(W) + (size_t)n * 32;
        #pragma unroll 4
        for (int c4 = 0; c4 < 32; c4++) {
            float4 w = __ldg(Wr + c4);
            #pragma unroll
            for (int jj = 0; jj < 8; jj++) {
                float4 x = Xs4[(half * 8 + jj) * 32 + c4];
                acc[jj] += x.x * w.x + x.y * w.y + x.z * w.z + x.w * w.w;
            }
        }
        #pragma unroll
        for (int jj = 0; jj < 8; jj++) {
            int j = j0 + half * 8 + jj;
            T[n][half * 8 + jj] = acc[jj];
            g_yh[(size_t)j * DIM + n] = __float2half_rn(acc[jj]);
        }
        __syncthreads();
        #pragma unroll
        for (int it = 0; it < 2; it++) {
            int idx = it * 256 + tid;
            int nn = idx >> 2, j4 = idx & 3;
            __half2 h0 = __floats2half2_rn(T[nn][j4 * 4], T[nn][j4 * 4 + 1]);
            __half2 h1 = __floats2half2_rn(T[nn][j4 * 4 + 2], T[nn][j4 * 4 + 3]);
            uint2 pk;
            pk.x = *reinterpret_cast<uint32_t*>(&h0);
            pk.y = *reinterpret_cast<uint32_t*>(&h1);
            *reinterpret_cast<uint2*>(&g_yt[(size_t)nn * NROWS + j0 + j4 * 4]) = pk;
        }
    } else {
        // ---- rowsum: dis = rsqrt(sum(A_row)+1) ----
        int row = blockIdx.x - ZBLK;
        const float4* r = A4 + (size_t)row * (NROWS / 4);
        float s = 0.f;
        #pragma unroll
        for (int p = 0; p < 8; p++) {
            float4 v = __ldcs(r + tid + p * 256);
            s += (v.x + v.y) + (v.z + v.w);
        }
        #pragma unroll
        for (int o = 16; o; o >>= 1) s += __shfl_xor_sync(0xffffffffu, s, o);
        if ((tid & 31) == 0) ws[tid >> 5] = s;
        __syncthreads();
        if (tid < 8) {
            float t = ws[tid];
            #pragma unroll
            for (int o = 4; o; o >>= 1) t += __shfl_xor_sync(0xffu, t, o);
            if (tid == 0) g_dis[row] = rsqrtf(t + 1.0f);
        }
    }
}

// ===================== kernel 2: split-K fp16 GEMM, dis folded into A conversion =====================
#define BM 256
#define BK 32
#define BSTGN 4
#define ASTR 40
#define AHSTG (BM * ASTR)
#define BSTR 40
#define BSTG (DIM * BSTR)
#define SMEM_BYTES ((2 * AHSTG + BSTGN * BSTG) * 2)  // 81920 B

static __device__ __forceinline__ void mma_f16(float* c, const uint32_t* a, const uint32_t* b) {
    asm volatile(
        "mma.sync.aligned.m16n8k16.row.col.f32.f16.f16.f32 "
        "{%0,%1,%2,%3}, {%4,%5,%6,%7}, {%8,%9}, {%0,%1,%2,%3};"
        : "+f"(c[0]), "+f"(c[1]), "+f"(c[2]), "+f"(c[3])
        : "r"(a[0]), "r"(a[1]), "r"(a[2]), "r"(a[3]), "r"(b[0]), "r"(b[1]));
}

static __device__ __forceinline__ void ldsm4(uint32_t* r, uint32_t addr) {
    asm volatile("ldmatrix.sync.aligned.m8n8.x4.shared.b16 {%0,%1,%2,%3}, [%4];"
                 : "=r"(r[0]), "=r"(r[1]), "=r"(r[2]), "=r"(r[3]) : "r"(addr));
}

__global__ void __launch_bounds__(256, 1) gemm_kernel(const float* __restrict__ A) {
    extern __shared__ __half smh[];
    __half* sAh = smh;                 // [2][AHSTG]
    __half* sB = smh + 2 * AHSTG;      // [BSTGN][BSTG]

    int tid = threadIdx.x, wid = tid >> 5, lane = tid & 31;
    int gid = lane >> 2, tig = lane & 3;
    const int m0 = blockIdx.x * BM;
    const int kbase = blockIdx.y * KSLICE;

    const int wm0 = (wid >> 1) * 64, wn0 = (wid & 1) * 64;

    float acc[4][8][4];
    #pragma unroll
    for (int mf = 0; mf < 4; mf++)
        #pragma unroll
        for (int nf = 0; nf < 8; nf++)
            #pragma unroll
            for (int q = 0; q < 4; q++) acc[mf][nf][q] = 0.f;

    const int a_row = lane & 15;
    const uint32_t a_koff = (uint32_t)(lane >> 4) * 16;
    const int b_row = (lane & 7) | ((lane >> 4) << 3);
    const uint32_t b_koff = (uint32_t)((lane >> 3) & 1) * 16;

    const int ar_r = tid >> 3, ar_c = tid & 7;
    float4 areg[8];
    float4 dis4;

    auto ldgA = [&](int stage) {
        int kk = kbase + stage * BK;
        const float* gp0 = A + (size_t)(m0 + ar_r) * NROWS + kk + ar_c * 4;
        dis4 = *reinterpret_cast<const float4*>(&g_dis[kk + ar_c * 4]);
        #pragma unroll
        for (int it = 0; it < 8; it++)
            areg[it] = __ldcs(reinterpret_cast<const float4*>(gp0 + (size_t)(it * 32) * NROWS));
    };
    auto stsA = [&](int slot) {
        __half* dst0 = sAh + slot * AHSTG + ar_r * ASTR + ar_c * 4;
        #pragma unroll
        for (int it = 0; it < 8; it++) {
            __half2 h0 = __floats2half2_rn(areg[it].x * dis4.x, areg[it].y * dis4.y);
            __half2 h1 = __floats2half2_rn(areg[it].z * dis4.z, areg[it].w * dis4.w);
            uint2 pk;
            pk.x = *reinterpret_cast<uint32_t*>(&h0);
            pk.y = *reinterpret_cast<uint32_t*>(&h1);
            *reinterpret_cast<uint2*>(dst0 + it * 32 * ASTR) = pk;
        }
    };
    auto issueB = [&](int stage, int buf) {
        int kk = kbase + stage * BK;
        #pragma unroll
        for (int it = 0; it < 2; it++) {
            int idx = it * 256 + tid;
            int r = idx >> 2, c = idx & 3;
            const __half* gp = g_yt + (size_t)r * NROWS + kk + c * 8;
            uint32_t sb = s2u(sB + buf * BSTG + r * BSTR + c * 8);
            asm volatile("cp.async.cg.shared.global [%0], [%1], 16;" :: "r"(sb), "l"(gp));
        }
        asm volatile("cp.async.commit_group;");
    };

    ldgA(0);
    issueB(0, 0); issueB(1, 1); issueB(2, 2);

    const int NS = KSLICE / BK;  // 64
    for (int i = 0; i < NS; i++) {
        stsA(i & 1);
        if (i + 1 < NS) ldgA(i + 1);
        asm volatile("cp.async.wait_group %0;" :: "n"(BSTGN - 2));
        __syncthreads();
        if (i + 3 < NS) issueB(i + 3, (i + 3) & (BSTGN - 1));

        uint32_t a_s = s2u(sAh + (i & 1) * AHSTG);
        uint32_t b_s = s2u(sB + (i & (BSTGN - 1)) * BSTG);

        #pragma unroll
        for (int ks = 0; ks < 2; ks++) {
            uint32_t k0h = ks * 16;
            uint32_t ar[4][4], br[4][4];
            #pragma unroll
            for (int mf = 0; mf < 4; mf++)
                ldsm4(ar[mf], a_s + 2u * ((wm0 + mf * 16 + a_row) * ASTR + k0h) + a_koff);
            #pragma unroll
            for (int t = 0; t < 4; t++)
                ldsm4(br[t], b_s + 2u * ((wn0 + t * 16 + b_row) * BSTR + k0h) + b_koff);
            #pragma unroll
            for (int mf = 0; mf < 4; mf++)
                #pragma unroll
                for (int t = 0; t < 4; t++) {
                    uint32_t bt0[2] = {br[t][0], br[t][1]};
                    uint32_t bt1[2] = {br[t][2], br[t][3]};
                    mma_f16(acc[mf][2 * t], ar[mf], bt0);
                    mma_f16(acc[mf][2 * t + 1], ar[mf], bt1);
                }
        }
    }

    __half* P = g_parth[blockIdx.y];
    #pragma unroll
    for (int mf = 0; mf < 4; mf++) {
        int r0 = m0 + wm0 + mf * 16 + gid;
        #pragma unroll
        for (int nf = 0; nf < 8; nf++) {
            int c = wn0 + nf * 8 + 2 * tig;
            __half2 p0 = __floats2half2_rn(acc[mf][nf][0], acc[mf][nf][1]);
            __half2 p1 = __floats2half2_rn(acc[mf][nf][2], acc[mf][nf][3]);
            *reinterpret_cast<__half2*>(&P[(size_t)r0 * DIM + c]) = p0;
            *reinterpret_cast<__half2*>(&P[(size_t)(r0 + 8) * DIM + c]) = p1;
        }
    }
}

// ===================== kernel 3: out = dis .* (sum P + dis .* Y) + b =====================
__global__ void __launch_bounds__(256) reduce_kernel(const float* __restrict__ bias,
                                                     float* __restrict__ out) {
    int idx = blockIdx.x * 256 + threadIdx.x;     // float4-out index
    int row = idx >> 5, n4 = idx & 31;
    uint2 p0 = *reinterpret_cast<const uint2*>(&g_parth[0][(size_t)idx * 4]);
    uint2 p1 = *reinterpret_cast<const uint2*>(&g_parth[1][(size_t)idx * 4]);
    uint2 p2 = *reinterpret_cast<const uint2*>(&g_parth[2][(size_t)idx * 4]);
    uint2 p3 = *reinterpret_cast<const uint2*>(&g_parth[3][(size_t)idx * 4]);
    uint2 yv = *reinterpret_cast<const uint2*>(&g_yh[(size_t)idx * 4]);
    float d = g_dis[row];
    float4 bb = __ldg(reinterpret_cast<const float4*>(bias) + n4);

    float2 a0 = __half22float2(*reinterpret_cast<__half2*>(&p0.x));
    float2 a1 = __half22float2(*reinterpret_cast<__half2*>(&p0.y));
    float2 b0 = __half22float2(*reinterpret_cast<__half2*>(&p1.x));
    float2 b1 = __half22float2(*reinterpret_cast<__half2*>(&p1.y));
    float2 c0 = __half22float2(*reinterpret_cast<__half2*>(&p2.x));
    float2 c1 = __half22float2(*reinterpret_cast<__half2*>(&p2.y));
    float2 e0 = __half22float2(*reinterpret_cast<__half2*>(&p3.x));
    float2 e1 = __half22float2(*reinterpret_cast<__half2*>(&p3.y));
    float2 y0 = __half22float2(*reinterpret_cast<__half2*>(&yv.x));
    float2 y1 = __half22float2(*reinterpret_cast<__half2*>(&yv.y));

    float4 o;
    o.x = d * (a0.x + b0.x + c0.x + e0.x + d * y0.x) + bb.x;
    o.y = d * (a0.y + b0.y + c0.y + e0.y + d * y0.y) + bb.y;
    o.z = d * (a1.x + b1.x + c1.x + e1.x + d * y1.x) + bb.z;
    o.w = d * (a1.y + b1.y + c1.y + e1.y + d * y1.y) + bb.w;
    reinterpret_cast<float4*>(out)[idx] = o;
}

// ===================== host =====================
extern "C" void kernel_launch(void* const* d_in, const int* in_sizes, int n_in,
                              void* d_out, int out_size) {
    const float* X = (const float*)d_in[0];
    const float* A = (const float*)d_in[1];
    const float* W = (const float*)d_in[2];
    const float* b = (const float*)d_in[3];
    float* out = (float*)d_out;

    prep_kernel<<<NROWS + ZBLK, 256>>>((const float4*)A, X, W);

    cudaFuncSetAttribute(gemm_kernel, cudaFuncAttributeMaxDynamicSharedMemorySize, SMEM_BYTES);
    gemm_kernel<<<dim3(NROWS / BM, KSPLIT), 256, SMEM_BYTES>>>(A);
    reduce_kernel<<<NROWS * DIM / 4 / 256, 256>>>(b, out);
}